// round 10
// baseline (speedup 1.0000x reference)
#include <cuda_runtime.h>
#include <cuda_bf16.h>
#include <cstdint>
#include <cstddef>

// MultiLayerLSTM via mma.sync (bf16 m16n8k16), fp32 bf16-split.
// A' = [batch-hi(64); batch-lo(64)] (M=128), N=32 gate rows/CTA, Whi+Wlo
// passes accumulated in registers. 512 threads: warp grid 4(m) x 2(n) x 2(k);
// kw groups split the 4 k-steps of each 64k sub-tile, folded via 2-pass Gr.
// Chunks of 128k (2 sub-tiles) halve sync count. 64+64 CTAs, decoupled
// per-layer progress counters.

#define T_ 1024
#define B_ 64
#define C_ 256
#define H_ 512
#define NTHR_ 512
#define GRID_ 128

// ---- shared memory byte offsets ----
#define OFF_BS  0                  // 32 float biases
#define OFF_GR  128                // 64 x 33 float gate matrix
#define OFF_A   9216               // 2 x 32KB A' chunk buffers (2 sub-tiles each)
#define OFF_WH  74752              // 16 x 4KB Whi 64k-chunk tiles
#define OFF_WL  140288             // 16 x 4KB Wlo 64k-chunk tiles
#define SMEM_BYTES 205824

typedef __nv_bfloat16 bf16;

static __device__ __align__(256) bf16 g_xhi[(size_t)T_ * B_ * C_];
static __device__ __align__(256) bf16 g_xlo[(size_t)T_ * B_ * C_];
static __device__ __align__(256) bf16 g_y0hi[(size_t)T_ * B_ * H_];
static __device__ __align__(256) bf16 g_y0lo[(size_t)T_ * B_ * H_];
static __device__ __align__(256) bf16 g_h1hi[(size_t)T_ * B_ * H_];
static __device__ __align__(256) bf16 g_h1lo[(size_t)T_ * B_ * H_];
static __device__ __align__(256) bf16 g_h00hi[B_ * H_], g_h00lo[B_ * H_];
static __device__ __align__(256) bf16 g_h01hi[B_ * H_], g_h01lo[B_ * H_];
static __device__ int g_bars0[8 * 32];
static __device__ int g_bars1[8 * 32];

__global__ void prep_kernel(const float* __restrict__ x,
                            const float* __restrict__ h00,
                            const float* __restrict__ h01) {
    const size_t stride = (size_t)gridDim.x * blockDim.x;
    const size_t i0 = (size_t)blockIdx.x * blockDim.x + threadIdx.x;
    const size_t nx = (size_t)T_ * B_ * C_;
    for (size_t p = i0; p < nx; p += stride) {
        float v = x[p];
        bf16 h = __float2bfloat16(v);
        g_xhi[p] = h;
        g_xlo[p] = __float2bfloat16(v - __bfloat162float(h));
    }
    for (size_t p = i0; p < (size_t)B_ * H_; p += stride) {
        float v = h00[p];
        bf16 h = __float2bfloat16(v);
        g_h00hi[p] = h;
        g_h00lo[p] = __float2bfloat16(v - __bfloat162float(h));
        v = h01[p];
        h = __float2bfloat16(v);
        g_h01hi[p] = h;
        g_h01lo[p] = __float2bfloat16(v - __bfloat162float(h));
    }
    if (blockIdx.x == 0 && threadIdx.x < 8) {
        g_bars0[threadIdx.x * 32] = 0;
        g_bars1[threadIdx.x * 32] = 0;
    }
}

__device__ __forceinline__ uint32_t smem_u32(const void* p) {
    uint32_t a;
    asm("{ .reg .u64 t; cvta.to.shared.u64 t, %1; cvt.u32.u64 %0, t; }"
        : "=r"(a) : "l"(p));
    return a;
}
__device__ __forceinline__ void ldsm4(uint32_t addr, uint32_t* r) {
    asm volatile("ldmatrix.sync.aligned.m8n8.x4.shared.b16 {%0,%1,%2,%3}, [%4];"
                 : "=r"(r[0]), "=r"(r[1]), "=r"(r[2]), "=r"(r[3]) : "r"(addr));
}
__device__ __forceinline__ void ldsm2(uint32_t addr, uint32_t* r) {
    asm volatile("ldmatrix.sync.aligned.m8n8.x2.shared.b16 {%0,%1}, [%2];"
                 : "=r"(r[0]), "=r"(r[1]) : "r"(addr));
}
__device__ __forceinline__ void mma16816(float* c, const uint32_t* a,
                                         const uint32_t* b) {
    asm volatile(
        "mma.sync.aligned.m16n8k16.row.col.f32.bf16.bf16.f32 "
        "{%0,%1,%2,%3}, {%4,%5,%6,%7}, {%8,%9}, {%0,%1,%2,%3};"
        : "+f"(c[0]), "+f"(c[1]), "+f"(c[2]), "+f"(c[3])
        : "r"(a[0]), "r"(a[1]), "r"(a[2]), "r"(a[3]), "r"(b[0]), "r"(b[1]));
}
__device__ __forceinline__ float sigf(float v) { return 1.0f / (1.0f + __expf(-v)); }

__device__ __forceinline__ void wait_bars(const int* bars, int tid, int target) {
    if (tid < 8) {
        volatile const int* p = bars + tid * 32;
        while (*p < target) { }
        __threadfence();
    }
    __syncthreads();
}

extern __shared__ char smem8[];

// stage one 128k A' chunk: rows 0-63 hi, 64-127 lo; two 64k SW128 sub-tiles
__device__ __forceinline__ void ldgA(const bf16* __restrict__ shi,
                                     const bf16* __restrict__ slo,
                                     int rs, int col0, int tid, uint4* v) {
    #pragma unroll
    for (int it = 0; it < 4; it++) {
        const int seg = it * NTHR_ + tid;       // 0..2047
        const int row = seg >> 4, s16 = seg & 15;
        const int st = s16 >> 3, s8 = s16 & 7;
        const bf16* src = (row < 64 ? shi + (size_t)row * rs
                                    : slo + (size_t)(row - 64) * rs)
                          + col0 + st * 64 + s8 * 8;
        v[it] = *(const uint4*)src;
    }
}
__device__ __forceinline__ void stsA(char* abuf, int tid, const uint4* v) {
    #pragma unroll
    for (int it = 0; it < 4; it++) {
        const int seg = it * NTHR_ + tid;
        const int row = seg >> 4, s16 = seg & 15;
        const int st = s16 >> 3, s8 = s16 & 7;
        const uint32_t bo = row * 128 + s8 * 16;
        const uint32_t sw = bo ^ ((bo >> 3) & 0x70);
        *(uint4*)(abuf + st * 16384 + sw) = v[it];
    }
}

__global__ void __launch_bounds__(NTHR_, 1) lstm_kernel(
    const float* __restrict__ x,
    const float* __restrict__ h00, const float* __restrict__ c00,
    const float* __restrict__ h01, const float* __restrict__ c01,
    const float* __restrict__ Wih0, const float* __restrict__ Whh0,
    const float* __restrict__ bih0, const float* __restrict__ bhh0,
    const float* __restrict__ Wih1, const float* __restrict__ Whh1,
    const float* __restrict__ bih1, const float* __restrict__ bhh1,
    float* out)
{
    const int tid  = threadIdx.x;
    const int wid  = tid >> 5;
    const int lid  = tid & 31;
    const int bid  = blockIdx.x;
    const int role = bid >> 6;            // 0: layer0, 1: layer1
    const int j0   = (bid & 63) * 8;
    const int grp  = (bid & 63) >> 3;

    const uint32_t sb = smem_u32(smem8);
    float* Bs = (float*)(smem8 + OFF_BS);
    float* Gr = (float*)(smem8 + OFF_GR);   // [64][33]

    const int KX = role ? H_ : C_;
    const int K  = KX + H_;
    const float* Wx    = role ? Wih1 : Wih0;
    const float* Wh    = role ? Whh1 : Whh0;
    const float* bi    = role ? bih1 : bih0;
    const float* bh    = role ? bhh1 : bhh0;
    const float* cinit = role ? c01 : c00;

    // ---- one-time: split weights into SW128 64k-chunk tiles (hi, lo) ----
    for (int idx = tid; idx < 32 * K; idx += NTHR_) {
        const int n = idx / K, k = idx - n * K;
        const int gr = (n >> 3) * H_ + j0 + (n & 7);
        const float v = (k < KX) ? Wx[(size_t)gr * KX + k]
                                 : Wh[(size_t)gr * H_ + (k - KX)];
        const bf16 hb = __float2bfloat16(v);
        const bf16 lb = __float2bfloat16(v - __bfloat162float(hb));
        const int wc = k >> 6, kk = k & 63;
        const uint32_t bo = n * 128 + kk * 2;
        const uint32_t sw = bo ^ ((bo >> 3) & 0x70);
        *(bf16*)(smem8 + OFF_WH + wc * 4096 + sw) = hb;
        *(bf16*)(smem8 + OFF_WL + wc * 4096 + sw) = lb;
    }
    if (tid < 32) {
        const int gr = (tid >> 3) * H_ + j0 + (tid & 7);
        Bs[tid] = bi[gr] + bh[gr];
    }
    float creg[8];
    if (tid < 64) {
        #pragma unroll
        for (int jj = 0; jj < 8; jj++)
            creg[jj] = cinit[(size_t)tid * H_ + j0 + jj];
    }
    __syncthreads();

    // warp decomposition: 4(m) x 2(n) x 2(k)
    const int w8 = wid & 7;
    const int mw = w8 & 3;
    const int nw = w8 >> 2;
    const int kw = wid >> 3;              // k-group: ks {0,1} or {2,3}
    // ldmatrix lane geometry
    const int jA = lid >> 3, rA = lid & 7;
    const int rowA  = ((jA & 1) << 3) + rA;
    const int colA2 = (jA >> 1) << 4;
    const uint32_t swA = (uint32_t)rA << 4;
    const int jB = (lid >> 3) & 1, rB = lid & 7;
    const int colB2 = jB << 4;
    const uint32_t swB = (uint32_t)rB << 4;
    const uint32_t aHiBase = (uint32_t)(16 * mw + rowA) * 128;
    const uint32_t aLoBase = (uint32_t)(64 + 16 * mw + rowA) * 128;
    const uint32_t bRow0   = (uint32_t)(16 * nw + rB) * 128;
    const uint32_t bRow1   = (uint32_t)(16 * nw + 8 + rB) * 128;

    float* yout = out;
    float* h1f  = out + (size_t)T_ * B_ * H_;
    float* c1f  = h1f + B_ * H_;
    float* h2f  = c1f + B_ * H_;
    float* c2f  = h2f + B_ * H_;
    float* hTd  = role ? h2f : h1f;
    float* cTd  = role ? c2f : c1f;
    int* actr   = (role ? g_bars1 : g_bars0) + grp * 32;

    for (int t = 0; t < T_; t++) {
        float acc[2][2][4];               // [hi/lo mtile][ntile][4]
        #pragma unroll
        for (int i = 0; i < 2; i++)
            #pragma unroll
            for (int j = 0; j < 2; j++)
                #pragma unroll
                for (int q = 0; q < 4; q++) acc[i][j][q] = 0.0f;

        int ab = 0;
        #pragma unroll 1
        for (int sg = 0; sg < 2; sg++) {
            // ---- resolve segment (chunks of 128k) ----
            const bf16 *shi, *slo;
            int rs, nch, wc0;             // wc0 in 64k units
            const int* bw; int tw;
            if (role == 0) {
                if (sg == 0) {            // x part, no wait
                    shi = g_xhi + (size_t)t * B_ * C_;
                    slo = g_xlo + (size_t)t * B_ * C_;
                    rs = C_; nch = 2; wc0 = 0; bw = nullptr; tw = 0;
                } else {                  // h part after own barrier
                    if (t == 0) { shi = g_h00hi; slo = g_h00lo; }
                    else {
                        shi = g_y0hi + (size_t)(t - 1) * B_ * H_;
                        slo = g_y0lo + (size_t)(t - 1) * B_ * H_;
                    }
                    rs = H_; nch = 4; wc0 = 4; bw = g_bars0; tw = t * 8;
                }
            } else {
                if (sg == 0) {            // h part after own barrier
                    if (t == 0) { shi = g_h01hi; slo = g_h01lo; }
                    else {
                        shi = g_h1hi + (size_t)(t - 1) * B_ * H_;
                        slo = g_h1lo + (size_t)(t - 1) * B_ * H_;
                    }
                    rs = H_; nch = 4; wc0 = 8; bw = g_bars1; tw = t * 8;
                } else {                  // y0 part after layer0 progress
                    shi = g_y0hi + (size_t)t * B_ * H_;
                    slo = g_y0lo + (size_t)t * B_ * H_;
                    rs = H_; nch = 4; wc0 = 0; bw = g_bars0; tw = (t + 1) * 8;
                }
            }
            if (bw) wait_bars(bw, tid, tw);

            {   // direct-stage first chunk
                uint4 v[4];
                ldgA(shi, slo, rs, 0, tid, v);
                stsA(smem8 + OFF_A + ab * 32768, tid, v);
            }
            for (int c = 0; c < nch; c++) {
                __syncthreads();          // staged buffer visible; other free
                uint4 v[4];
                const bool pf = (c + 1 < nch);
                if (pf) ldgA(shi, slo, rs, (c + 1) * 128, tid, v);

                // ---- compute chunk: 2 sub-tiles x (2 ks for this kw) ----
                #pragma unroll
                for (int st = 0; st < 2; st++) {
                    const uint32_t aBase = sb + OFF_A + ab * 32768 + st * 16384;
                    const uint32_t wcb   = (uint32_t)(wc0 + 2 * c + st) * 4096;
                    const uint32_t whB   = sb + OFF_WH + wcb;
                    const uint32_t wlB   = sb + OFF_WL + wcb;
                    #pragma unroll
                    for (int kq = 0; kq < 2; kq++) {
                        const int ks = kw * 2 + kq;
                        const uint32_t kA = (uint32_t)((ks * 32 + colA2) ^ (int)swA);
                        const uint32_t kB = (uint32_t)((ks * 32 + colB2) ^ (int)swB);
                        uint32_t ah[4], al[4], bh0[2], bh1[2], bl0[2], bl1[2];
                        ldsm4(aBase + aHiBase + kA, ah);
                        ldsm4(aBase + aLoBase + kA, al);
                        ldsm2(whB + bRow0 + kB, bh0);
                        ldsm2(whB + bRow1 + kB, bh1);
                        ldsm2(wlB + bRow0 + kB, bl0);
                        ldsm2(wlB + bRow1 + kB, bl1);
                        mma16816(acc[0][0], ah, bh0);
                        mma16816(acc[0][1], ah, bh1);
                        mma16816(acc[1][0], al, bh0);
                        mma16816(acc[1][1], al, bh1);
                        mma16816(acc[0][0], ah, bl0);
                        mma16816(acc[0][1], ah, bl1);
                        mma16816(acc[1][0], al, bl0);
                        mma16816(acc[1][1], al, bl1);
                    }
                }
                if (pf) stsA(smem8 + OFF_A + (ab ^ 1) * 32768, tid, v);
                ab ^= 1;
            }
        }
        __syncthreads();

        // ---- fold: kw0 writes (hi+lo), kw1 accumulates ----
        {
            const int mrow = 16 * mw + (lid >> 2);
            const int col0 = 16 * nw + 2 * (lid & 3);
            if (kw == 0) {
                #pragma unroll
                for (int nt = 0; nt < 2; nt++) {
                    const int cc = col0 + nt * 8;
                    Gr[mrow * 33 + cc]           = acc[0][nt][0] + acc[1][nt][0];
                    Gr[mrow * 33 + cc + 1]       = acc[0][nt][1] + acc[1][nt][1];
                    Gr[(mrow + 8) * 33 + cc]     = acc[0][nt][2] + acc[1][nt][2];
                    Gr[(mrow + 8) * 33 + cc + 1] = acc[0][nt][3] + acc[1][nt][3];
                }
            }
            __syncthreads();
            if (kw == 1) {
                #pragma unroll
                for (int nt = 0; nt < 2; nt++) {
                    const int cc = col0 + nt * 8;
                    Gr[mrow * 33 + cc]           += acc[0][nt][0] + acc[1][nt][0];
                    Gr[mrow * 33 + cc + 1]       += acc[0][nt][1] + acc[1][nt][1];
                    Gr[(mrow + 8) * 33 + cc]     += acc[0][nt][2] + acc[1][nt][2];
                    Gr[(mrow + 8) * 33 + cc + 1] += acc[0][nt][3] + acc[1][nt][3];
                }
            }
        }
        __syncthreads();

        // ---- pointwise + h/c update (threads 0-63 = batch rows) ----
        if (tid < 64) {
            const int m = tid;
            float hv[8];
            #pragma unroll
            for (int jj = 0; jj < 8; jj++) {
                float gi = Gr[m * 33 + jj]      + Bs[jj];
                float gf = Gr[m * 33 + 8 + jj]  + Bs[8 + jj];
                float gg = Gr[m * 33 + 16 + jj] + Bs[16 + jj];
                float go = Gr[m * 33 + 24 + jj] + Bs[24 + jj];
                gi = sigf(gi); gf = sigf(gf); gg = tanhf(gg); go = sigf(go);
                const float cv = gf * creg[jj] + gi * gg;
                creg[jj] = cv;
                hv[jj] = go * tanhf(cv);
            }
            uint32_t phh[4], pll[4];
            #pragma unroll
            for (int q = 0; q < 4; q++) {
                const float a = hv[2 * q], b = hv[2 * q + 1];
                const bf16 ba = __float2bfloat16(a), bb = __float2bfloat16(b);
                phh[q] = (uint32_t)__bfloat16_as_ushort(ba) |
                         ((uint32_t)__bfloat16_as_ushort(bb) << 16);
                const bf16 la = __float2bfloat16(a - __bfloat162float(ba));
                const bf16 lb = __float2bfloat16(b - __bfloat162float(bb));
                pll[q] = (uint32_t)__bfloat16_as_ushort(la) |
                         ((uint32_t)__bfloat16_as_ushort(lb) << 16);
            }
            bf16* dsthi = (role ? g_h1hi : g_y0hi) + (size_t)t * B_ * H_
                          + (size_t)m * H_ + j0;
            bf16* dstlo = (role ? g_h1lo : g_y0lo) + (size_t)t * B_ * H_
                          + (size_t)m * H_ + j0;
            *(uint4*)dsthi = make_uint4(phh[0], phh[1], phh[2], phh[3]);
            *(uint4*)dstlo = make_uint4(pll[0], pll[1], pll[2], pll[3]);
            if (role) {
                float* od = yout + (size_t)t * B_ * H_ + (size_t)m * H_ + j0;
                *(float4*)od       = make_float4(hv[0], hv[1], hv[2], hv[3]);
                *(float4*)(od + 4) = make_float4(hv[4], hv[5], hv[6], hv[7]);
            }
            if (t == T_ - 1) {
                float* hd = hTd + (size_t)m * H_ + j0;
                *(float4*)hd       = make_float4(hv[0], hv[1], hv[2], hv[3]);
                *(float4*)(hd + 4) = make_float4(hv[4], hv[5], hv[6], hv[7]);
                float* cd = cTd + (size_t)m * H_ + j0;
                *(float4*)cd       = make_float4(creg[0], creg[1], creg[2], creg[3]);
                *(float4*)(cd + 4) = make_float4(creg[4], creg[5], creg[6], creg[7]);
            }
            __threadfence();
        }
        __syncthreads();
        if (tid == 0) atomicAdd(actr, 1);
    }
}

extern "C" void kernel_launch(void* const* d_in, const int* in_sizes, int n_in,
                              void* d_out, int out_size) {
    (void)in_sizes; (void)n_in; (void)out_size;
    cudaFuncSetAttribute(lstm_kernel, cudaFuncAttributeMaxDynamicSharedMemorySize,
                         SMEM_BYTES);
    prep_kernel<<<1024, 256>>>((const float*)d_in[0], (const float*)d_in[1],
                               (const float*)d_in[3]);
    lstm_kernel<<<GRID_, NTHR_, SMEM_BYTES>>>(
        (const float*)d_in[0],
        (const float*)d_in[1], (const float*)d_in[2],
        (const float*)d_in[3], (const float*)d_in[4],
        (const float*)d_in[5], (const float*)d_in[6],
        (const float*)d_in[7], (const float*)d_in[8],
        (const float*)d_in[9], (const float*)d_in[10],
        (const float*)d_in[11], (const float*)d_in[12],
        (float*)d_out);
}